// round 1
// baseline (speedup 1.0000x reference)
#include <cuda_runtime.h>

#define MAX_NODES 100000
#define MAX_EDGES 1250000
#define FDIM 64

// ---------------- static device scratch (no runtime allocation) ----------------
__device__ int   g_counts[MAX_NODES + 1];   // histogram -> exclusive offsets
__device__ int   g_cursor[MAX_NODES];       // scatter cursors
__device__ int   g_blocksums[256];          // scan spine
__device__ float4 g_epack[MAX_EDGES];       // per-edge packed (sender, w_s2d, w_d2s, pad), CSR order
__device__ float g_agg0[(size_t)MAX_NODES * FDIM];  // agg_s2d
__device__ float g_agg1[(size_t)MAX_NODES * FDIM];  // agg_d2s

// ---------------- helpers: packed f32x2 FMA (sm_100+) ----------------
__device__ __forceinline__ unsigned long long dup2(float a) {
    unsigned long long r;
    asm("mov.b64 %0, {%1, %1};" : "=l"(r) : "f"(a));
    return r;
}
__device__ __forceinline__ void fma2(unsigned long long& d, unsigned long long a, unsigned long long b) {
    asm("fma.rn.f32x2 %0, %1, %2, %0;" : "+l"(d) : "l"(a), "l"(b));
}
__device__ __forceinline__ float2 unpack2(unsigned long long v) {
    float2 r;
    asm("mov.b64 {%0, %1}, %2;" : "=f"(r.x), "=f"(r.y) : "l"(v));
    return r;
}

// ---------------- K0: zero histogram ----------------
__global__ void k_zero_counts(int n_total) {  // n_total = nNodes + 1
    int i = blockIdx.x * blockDim.x + threadIdx.x;
    if (i < n_total) g_counts[i] = 0;
}

// ---------------- K1: histogram of receivers ----------------
__global__ void k_hist(const int* __restrict__ recv, int nE) {
    int e = blockIdx.x * blockDim.x + threadIdx.x;
    if (e < nE) atomicAdd(&g_counts[recv[e]], 1);
}

// ---------------- K2: per-block exclusive scan (1024 elems/block) ----------------
__global__ void k_scan1(int n) {  // n = nNodes + 1
    __shared__ int sm[1024];
    int t = threadIdx.x;
    int i = blockIdx.x * 1024 + t;
    int v = (i < n) ? g_counts[i] : 0;
    int val = v;
    sm[t] = val;
    __syncthreads();
    #pragma unroll
    for (int off = 1; off < 1024; off <<= 1) {
        int other = (t >= off) ? sm[t - off] : 0;
        __syncthreads();
        val += other;
        sm[t] = val;
        __syncthreads();
    }
    if (i < n) g_counts[i] = val - v;      // local exclusive
    if (t == 1023) g_blocksums[blockIdx.x] = val;  // block total
}

// ---------------- K3: scan the spine (tiny, serial) ----------------
__global__ void k_scan2(int nb) {
    if (threadIdx.x == 0 && blockIdx.x == 0) {
        int run = 0;
        for (int b = 0; b < nb; b++) {
            int v = g_blocksums[b];
            g_blocksums[b] = run;
            run += v;
        }
    }
}

// ---------------- K4: add spine offsets, init cursors ----------------
__global__ void k_scan3(int n, int nNodes) {  // n = nNodes + 1
    int i = blockIdx.x * blockDim.x + threadIdx.x;
    if (i < n) {
        int v = g_counts[i] + g_blocksums[i >> 10];
        g_counts[i] = v;              // final exclusive offsets; g_counts[nNodes] == nE
        if (i < nNodes) g_cursor[i] = v;
    }
}

// ---------------- K5: scatter edges into CSR order, packing metadata ----------------
__global__ void k_scatter(const int* __restrict__ recv, const int* __restrict__ send,
                          const float* __restrict__ ew0, const float* __restrict__ ew1,
                          int nE) {
    int e = blockIdx.x * blockDim.x + threadIdx.x;
    if (e < nE) {
        int r = recv[e];
        int pos = atomicAdd(&g_cursor[r], 1);
        g_epack[pos] = make_float4(__int_as_float(send[e]), ew0[e], ew1[e], 0.0f);
    }
}

// ---------------- K6: atomic-free aggregation, warp per node ----------------
__global__ void __launch_bounds__(256) k_aggregate(const float* __restrict__ x, int nNodes) {
    int lane = threadIdx.x & 31;
    int node = (blockIdx.x * blockDim.x + threadIdx.x) >> 5;
    if (node >= nNodes) return;

    int s0 = g_counts[node];
    int s1 = g_counts[node + 1];

    float a0x = 0.f, a0y = 0.f, a1x = 0.f, a1y = 0.f;
    #pragma unroll 2
    for (int i = s0; i < s1; i++) {
        float4 m = g_epack[i];                       // broadcast LDG.128 across warp
        int s = __float_as_int(m.x);
        float2 v = *reinterpret_cast<const float2*>(x + (size_t)s * FDIM + (lane << 1));
        a0x = fmaf(m.y, v.x, a0x);
        a0y = fmaf(m.y, v.y, a0y);
        a1x = fmaf(m.z, v.x, a1x);
        a1y = fmaf(m.z, v.y, a1y);
    }
    size_t base = (size_t)node * FDIM + (lane << 1);
    *reinterpret_cast<float2*>(&g_agg0[base]) = make_float2(a0x, a0y);
    *reinterpret_cast<float2*>(&g_agg1[base]) = make_float2(a1x, a1y);
}

// ---------------- K7: reg-tiled fp32 GEMM (out = agg @ W + b), f32x2 FMA ----------------
// BM=128 rows, BN=64 cols (full), K=64 (full). 128 threads, 8x8 microtile.
#define GEMM_BM 128
__global__ void __launch_bounds__(128) k_gemm(const float* __restrict__ W0,
                                              const float* __restrict__ W1,
                                              const float* __restrict__ b0,
                                              const float* __restrict__ b1,
                                              float* __restrict__ out, int nNodes) {
    const int mat = blockIdx.y;
    const float* __restrict__ A    = mat ? g_agg1 : g_agg0;
    const float* __restrict__ W    = mat ? W1 : W0;
    const float* __restrict__ bias = mat ? b1 : b0;
    float* __restrict__ O = out + (size_t)mat * nNodes * FDIM;

    __shared__ float As[FDIM][GEMM_BM + 4];  // K-major A tile: As[k][m]
    __shared__ float Ws[FDIM][FDIM + 4];     // Ws[k][n]

    const int tid = threadIdx.x;             // 0..127
    const int m_blk = blockIdx.x * GEMM_BM;

    // Load + transpose A tile (128 rows x 64 k), 2048 float4 loads total
    #pragma unroll
    for (int it = 0; it < 16; it++) {
        int f = it * 128 + tid;              // [0, 2048)
        int row = f >> 4;                    // 0..127
        int kq  = f & 15;                    // k-quad
        int gm = m_blk + row;
        float4 v = (gm < nNodes)
            ? *reinterpret_cast<const float4*>(A + (size_t)gm * FDIM + kq * 4)
            : make_float4(0.f, 0.f, 0.f, 0.f);
        As[kq * 4 + 0][row] = v.x;
        As[kq * 4 + 1][row] = v.y;
        As[kq * 4 + 2][row] = v.z;
        As[kq * 4 + 3][row] = v.w;
    }
    // Load W (64x64), natural layout
    #pragma unroll
    for (int it = 0; it < 8; it++) {
        int f = it * 128 + tid;              // [0, 1024)
        int k  = f >> 4;
        int nq = f & 15;
        float4 v = *reinterpret_cast<const float4*>(W + k * FDIM + nq * 4);
        *reinterpret_cast<float4*>(&Ws[k][nq * 4]) = v;
    }
    __syncthreads();

    const int tm = tid >> 3;                 // 0..15
    const int tn = tid & 7;                  // 0..7
    const int m0 = tm * 8;
    const int n0 = tn * 8;

    unsigned long long acc[8][4];
    #pragma unroll
    for (int i = 0; i < 8; i++)
        #pragma unroll
        for (int j = 0; j < 4; j++) acc[i][j] = 0ULL;

    #pragma unroll
    for (int k = 0; k < FDIM; k++) {
        unsigned long long ad[8];
        #pragma unroll
        for (int i = 0; i < 8; i++) ad[i] = dup2(As[k][m0 + i]);
        const unsigned long long* wrow =
            reinterpret_cast<const unsigned long long*>(&Ws[k][n0]);
        unsigned long long w0 = wrow[0], w1 = wrow[1], w2 = wrow[2], w3 = wrow[3];
        #pragma unroll
        for (int i = 0; i < 8; i++) {
            fma2(acc[i][0], ad[i], w0);
            fma2(acc[i][1], ad[i], w1);
            fma2(acc[i][2], ad[i], w2);
            fma2(acc[i][3], ad[i], w3);
        }
    }

    float bj[8];
    #pragma unroll
    for (int j = 0; j < 8; j++) bj[j] = bias[n0 + j];

    #pragma unroll
    for (int i = 0; i < 8; i++) {
        int gm = m_blk + m0 + i;
        if (gm < nNodes) {
            float2 p0 = unpack2(acc[i][0]);
            float2 p1 = unpack2(acc[i][1]);
            float2 p2 = unpack2(acc[i][2]);
            float2 p3 = unpack2(acc[i][3]);
            float4 o0 = make_float4(p0.x + bj[0], p0.y + bj[1], p1.x + bj[2], p1.y + bj[3]);
            float4 o1 = make_float4(p2.x + bj[4], p2.y + bj[5], p3.x + bj[6], p3.y + bj[7]);
            float* dst = O + (size_t)gm * FDIM + n0;
            *reinterpret_cast<float4*>(dst)     = o0;
            *reinterpret_cast<float4*>(dst + 4) = o1;
        }
    }
}

// ---------------- launch ----------------
extern "C" void kernel_launch(void* const* d_in, const int* in_sizes, int n_in,
                              void* d_out, int out_size) {
    const float* x     = (const float*)d_in[0];
    const int*   ei    = (const int*)d_in[1];
    const float* ew    = (const float*)d_in[2];
    const float* W_src = (const float*)d_in[3];
    const float* W_dst = (const float*)d_in[4];
    const float* b_src = (const float*)d_in[5];
    const float* b_dst = (const float*)d_in[6];
    float* out = (float*)d_out;

    const int nNodes = in_sizes[0] / FDIM;
    const int nEdges = in_sizes[1] / 2;

    const int* senders = ei;
    const int* recv    = ei + nEdges;
    const float* ew0   = ew;            // s2d weights
    const float* ew1   = ew + nEdges;   // d2s weights

    const int nOff = nNodes + 1;

    // K0: zero histogram
    k_zero_counts<<<(nOff + 1023) / 1024, 1024>>>(nOff);
    // K1: histogram
    k_hist<<<(nEdges + 255) / 256, 256>>>(recv, nEdges);
    // K2..K4: exclusive scan -> offsets + cursors
    int nb = (nOff + 1023) / 1024;
    k_scan1<<<nb, 1024>>>(nOff);
    k_scan2<<<1, 32>>>(nb);
    k_scan3<<<nb, 1024>>>(nOff, nNodes);
    // K5: CSR scatter with packed metadata
    k_scatter<<<(nEdges + 255) / 256, 256>>>(recv, senders, ew0, ew1, nEdges);
    // K6: atomic-free aggregation (warp per node)
    int aggBlocks = (nNodes * 32 + 255) / 256;
    k_aggregate<<<aggBlocks, 256>>>(x, nNodes);
    // K7: two GEMMs (out_s2d, out_d2s)
    dim3 gg((nNodes + GEMM_BM - 1) / GEMM_BM, 2);
    k_gemm<<<gg, 128>>>(W_src, W_dst, b_src, b_dst, out, nNodes);
}